// round 4
// baseline (speedup 1.0000x reference)
#include <cuda_runtime.h>

// Problem constants (from reference)
#define BB 16
#define AA 128
#define PP 8192
#define TT 5
#define K_LOG2E 1.4426950408889634f   // log2(e); TEMPERATURE = 1.0
#define LN2F    0.6931471805599453f
#define CLIP    0.3f

#define THREADS 256          // 8 warps/block
#define QPB THREADS          // 1 query per thread
#define MAXP 80              // max packed atom-pairs (128 atoms + padding)/2

__device__ __forceinline__ float ex2f_a(float x) {
    float y; asm("ex2.approx.ftz.f32 %0, %1;" : "=f"(y) : "f"(x)); return y;
}
__device__ __forceinline__ float sqrtf_a(float x) {
    float y; asm("sqrt.approx.ftz.f32 %0, %1;" : "=f"(y) : "f"(x)); return y;
}
__device__ __forceinline__ float rcpf_a(float x) {
    float y; asm("rcp.approx.ftz.f32 %0, %1;" : "=f"(y) : "f"(x)); return y;
}
__device__ __forceinline__ float rsqrtf_a(float x) {
    float y; asm("rsqrt.approx.ftz.f32 %0, %1;" : "=f"(y) : "f"(x)); return y;
}

// ---- packed f32x2 helpers (sm_100 FFMA2/FADD2/FMUL2 via PTX) ----
typedef unsigned long long ull;
__device__ __forceinline__ ull f2_pack(float lo, float hi) {
    ull r; asm("mov.b64 %0, {%1, %2};" : "=l"(r) : "f"(lo), "f"(hi)); return r;
}
__device__ __forceinline__ void f2_unpack(float& lo, float& hi, ull v) {
    asm("mov.b64 {%0, %1}, %2;" : "=f"(lo), "=f"(hi) : "l"(v));
}
__device__ __forceinline__ ull f2_add(ull a, ull b) {
    ull d; asm("add.rn.f32x2 %0, %1, %2;" : "=l"(d) : "l"(a), "l"(b)); return d;
}
__device__ __forceinline__ ull f2_mul(ull a, ull b) {
    ull d; asm("mul.rn.f32x2 %0, %1, %2;" : "=l"(d) : "l"(a), "l"(b)); return d;
}
__device__ __forceinline__ ull f2_fma(ull a, ull b, ull c) {
    ull d; asm("fma.rn.f32x2 %0, %1, %2, %3;" : "=l"(d) : "l"(a), "l"(b), "l"(c)); return d;
}
__device__ __forceinline__ float fnegbit(float x) {   // sign flip on ALU pipe (LOP3)
    return __uint_as_float(__float_as_uint(x) ^ 0x80000000u);
}

__global__ void __launch_bounds__(THREADS)
gnf_kernel(const float* __restrict__ coords,     // [B, A, 3] f32
           const int*   __restrict__ types_raw,  // [B, A] int32 OR int64 (detected)
           const float* __restrict__ query,      // [B, P, 3] f32
           float*       __restrict__ out)        // [B, P, T, 3] f32
{
    // packed atom-pair arrays: sX[j] = (x_{2j}, x_{2j+1}) etc., 8-byte aligned
    __shared__ ull sX[MAXP], sY[MAXP], sZ[MAXP];
    __shared__ int sStart[TT + 1];   // padded segment starts (in atoms, multiple of 4)
    __shared__ int sCnt[TT];
    __shared__ int sOffs[TT];

    float* fX = (float*)sX;
    float* fY = (float*)sY;
    float* fZ = (float*)sZ;

    const int tid = threadIdx.x;
    const int b   = blockIdx.y;

    // ---- sentinel fill: w = ex2(-sqrt(~1e30)) == 0 exactly (ftz), no NaN
    for (int j = tid; j < MAXP; j += THREADS) {
        sX[j] = 0x58DE0B6B58DE0B6BULL;   // (1e15f, 1e15f)
        sY[j] = 0ULL;
        sZ[j] = 0ULL;
    }
    if (tid < TT) sCnt[tid] = 0;

    // ---- dtype detection: int64 iff every odd 32-bit word is 0 or -1
    bool ok = true;
    #pragma unroll 2
    for (int i = tid; i < (BB * AA) / 2; i += THREADS) {
        int w = types_raw[2 * i + 1];
        if (w != 0 && w != -1) ok = false;
    }
    const int is64 = __syncthreads_and(ok ? 1 : 0);  // also fences sentinel fill

    // ---- counting sort by type (threads 0..127), segments padded to 4 atoms
    int t_mine = -1;
    if (tid < AA) {
        long long tv;
        if (is64) tv = ((const long long*)types_raw)[(long)b * AA + tid];
        else      tv = (long long)types_raw[(long)b * AA + tid];
        if (tv >= 0 && tv < TT) {
            t_mine = (int)tv;
            atomicAdd(&sCnt[t_mine], 1);
        }
    }
    __syncthreads();
    if (tid == 0) {
        int s = 0;
        #pragma unroll
        for (int k = 0; k < TT; k++) {
            sStart[k] = s; sOffs[k] = s;
            s += (sCnt[k] + 3) & ~3;     // pad to multiple of 4 atoms (2 pairs)
        }
        sStart[TT] = s;
    }
    __syncthreads();
    if (t_mine >= 0) {
        int pos = atomicAdd(&sOffs[t_mine], 1);
        const float* c = coords + ((long)b * AA + tid) * 3;
        fX[pos] = c[0] * K_LOG2E;
        fY[pos] = c[1] * K_LOG2E;
        fZ[pos] = c[2] * K_LOG2E;
    }
    __syncthreads();

    // ---- one query point per thread; negated & broadcast into both lanes
    const int q0 = blockIdx.x * QPB + tid;
    const float* qp = query + ((long)b * PP + q0) * 3;
    const float qx = qp[0] * K_LOG2E, qy = qp[1] * K_LOG2E, qz = qp[2] * K_LOG2E;
    const ull nqx = f2_pack(-qx, -qx);
    const ull nqy = f2_pack(-qy, -qy);
    const ull nqz = f2_pack(-qz, -qz);

    float* outp = out + ((long)b * PP + q0) * (TT * 3);

    #pragma unroll
    for (int t = 0; t < TT; t++) {
        const int ps = sStart[t] >> 1;                       // even
        const int pe = (sStart[t + 1]) >> 1;                 // ps + multiple of 2
        ull S0 = 0, Gx0 = 0, Gy0 = 0, Gz0 = 0;               // (0,0) packed
        ull S1 = 0, Gx1 = 0, Gy1 = 0, Gz1 = 0;

        for (int j = ps; j < pe; j += 2) {
            // stream 0: pair j
            const ull cx0 = sX[j], cy0 = sY[j], cz0 = sZ[j];
            // stream 1: pair j+1
            const ull cx1 = sX[j + 1], cy1 = sY[j + 1], cz1 = sZ[j + 1];

            ull dx0 = f2_add(cx0, nqx), dy0 = f2_add(cy0, nqy), dz0 = f2_add(cz0, nqz);
            ull dx1 = f2_add(cx1, nqx), dy1 = f2_add(cy1, nqy), dz1 = f2_add(cz1, nqz);

            ull d2p0 = f2_fma(dx0, dx0, f2_fma(dy0, dy0, f2_mul(dz0, dz0)));
            ull d2p1 = f2_fma(dx1, dx1, f2_fma(dy1, dy1, f2_mul(dz1, dz1)));

            float a0, b0, a1, b1;
            f2_unpack(a0, b0, d2p0);
            f2_unpack(a1, b1, d2p1);

            float wa0 = ex2f_a(fnegbit(sqrtf_a(a0)));
            float wb0 = ex2f_a(fnegbit(sqrtf_a(b0)));
            float wa1 = ex2f_a(fnegbit(sqrtf_a(a1)));
            float wb1 = ex2f_a(fnegbit(sqrtf_a(b1)));

            ull w0 = f2_pack(wa0, wb0);
            ull w1 = f2_pack(wa1, wb1);

            S0  = f2_add(S0, w0);
            Gx0 = f2_fma(w0, dx0, Gx0);
            Gy0 = f2_fma(w0, dy0, Gy0);
            Gz0 = f2_fma(w0, dz0, Gz0);

            S1  = f2_add(S1, w1);
            Gx1 = f2_fma(w1, dx1, Gx1);
            Gy1 = f2_fma(w1, dy1, Gy1);
            Gz1 = f2_fma(w1, dz1, Gz1);
        }

        // horizontal reduce the 4 partial lanes
        float u, v; float S, Gx, Gy, Gz;
        f2_unpack(u, v, f2_add(S0, S1));   S  = u + v;
        f2_unpack(u, v, f2_add(Gx0, Gx1)); Gx = u + v;
        f2_unpack(u, v, f2_add(Gy0, Gy1)); Gy = u + v;
        f2_unpack(u, v, f2_add(Gz0, Gz1)); Gz = u + v;

        // finalize: grad = (G/S)/log2(e); clip to norm 0.3; empty type -> 0
        float inv = (S > 0.f) ? rcpf_a(S) * LN2F : 0.f;
        float gx = Gx * inv, gy = Gy * inv, gz = Gz * inv;
        float m2 = fmaf(gx, gx, fmaf(gy, gy, gz * gz));
        if (m2 > CLIP * CLIP) {
            float sc = CLIP * rsqrtf_a(m2);
            gx *= sc; gy *= sc; gz *= sc;
        }
        outp[t * 3 + 0] = gx; outp[t * 3 + 1] = gy; outp[t * 3 + 2] = gz;
    }
}

extern "C" void kernel_launch(void* const* d_in, const int* in_sizes, int n_in,
                              void* d_out, int out_size)
{
    const float* coords = (const float*)d_in[0];   // [16,128,3] f32
    const int*   types  = (const int*)d_in[1];     // [16,128] int32/int64 (detected on device)
    const float* query  = (const float*)d_in[2];   // [16,8192,3] f32
    float*       out    = (float*)d_out;           // [16,8192,5,3] f32

    dim3 grid(PP / QPB, BB);   // (32, 16) = 512 blocks x 256 threads
    gnf_kernel<<<grid, THREADS>>>(coords, types, query, out);
}

// round 5
// speedup vs baseline: 1.0340x; 1.0340x over previous
#include <cuda_runtime.h>

// Problem constants (from reference)
#define BB 16
#define AA 128
#define PP 8192
#define TT 5
#define K_LOG2E 1.4426950408889634f   // log2(e); TEMPERATURE = 1.0
#define LN2F    0.6931471805599453f
#define CLIP    0.3f

#define THREADS 256          // 8 warps/block
#define QPB 128              // queries per block: 2 threads cooperate per query
#define MAXA 160             // 128 atoms + up to 5*3 pad, rounded up

__device__ __forceinline__ float ex2f_a(float x) {
    float y; asm("ex2.approx.ftz.f32 %0, %1;" : "=f"(y) : "f"(x)); return y;
}
__device__ __forceinline__ float sqrtf_a(float x) {
    float y; asm("sqrt.approx.ftz.f32 %0, %1;" : "=f"(y) : "f"(x)); return y;
}
__device__ __forceinline__ float rcpf_a(float x) {
    float y; asm("rcp.approx.ftz.f32 %0, %1;" : "=f"(y) : "f"(x)); return y;
}
__device__ __forceinline__ float rsqrtf_a(float x) {
    float y; asm("rsqrt.approx.ftz.f32 %0, %1;" : "=f"(y) : "f"(x)); return y;
}

__global__ void __launch_bounds__(THREADS)
gnf_kernel(const float* __restrict__ coords,     // [B, A, 3] f32
           const int*   __restrict__ types_raw,  // [B, A] int32 OR int64 (detected)
           const float* __restrict__ query,      // [B, P, 3] f32
           float*       __restrict__ out)        // [B, P, T, 3] f32
{
    __shared__ float4 satoms[MAXA];     // type-sorted, scaled coords (+sentinel pad)
    __shared__ int    sStart[TT + 1];   // padded starts, multiples of 4
    __shared__ int    sCnt[TT];
    __shared__ int    sOffs[TT];

    const int tid = threadIdx.x;
    const int b   = blockIdx.y;

    // ---- sentinel fill: dist ~ sqrt(3e30) -> ex2(-1.7e15) == 0 exactly, no NaN
    for (int j = tid; j < MAXA; j += THREADS)
        satoms[j] = make_float4(1e15f, 0.f, 0.f, 0.f);
    if (tid < TT) sCnt[tid] = 0;

    // ---- dtype detection: int64 iff every odd 32-bit word is 0 or -1
    bool ok = true;
    #pragma unroll 2
    for (int i = tid; i < (BB * AA) / 2; i += THREADS) {
        int w = types_raw[2 * i + 1];
        if (w != 0 && w != -1) ok = false;
    }
    const int is64 = __syncthreads_and(ok ? 1 : 0);  // also fences sentinel fill

    // ---- counting sort of this batch's 128 atoms by type, segments padded to x4
    int t_mine = -1;
    if (tid < AA) {
        long long tv;
        if (is64) tv = ((const long long*)types_raw)[(long)b * AA + tid];
        else      tv = (long long)types_raw[(long)b * AA + tid];
        if (tv >= 0 && tv < TT) {
            t_mine = (int)tv;
            atomicAdd(&sCnt[t_mine], 1);
        }
    }
    __syncthreads();
    if (tid == 0) {
        int s = 0;
        #pragma unroll
        for (int k = 0; k < TT; k++) {
            sStart[k] = s; sOffs[k] = s;
            s += (sCnt[k] + 3) & ~3;     // pad each segment to multiple of 4 atoms
        }
        sStart[TT] = s;
    }
    __syncthreads();
    if (t_mine >= 0) {
        int pos = atomicAdd(&sOffs[t_mine], 1);
        const float* c = coords + ((long)b * AA + tid) * 3;
        satoms[pos] = make_float4(c[0] * K_LOG2E, c[1] * K_LOG2E, c[2] * K_LOG2E, 0.f);
    }
    __syncthreads();

    // ---- 2 threads per query: lanes l and l^16 of each warp share query
    //      warp w covers queries qbase + w*16 + (l & 15); h = l>>4 picks atom half
    const int warp = tid >> 5;
    const int lane = tid & 31;
    const int h    = lane >> 4;                       // 0 or 1: my atom half
    const int q0   = blockIdx.x * QPB + warp * 16 + (lane & 15);

    const float* qp = query + ((long)b * PP + q0) * 3;
    const float qx = qp[0] * K_LOG2E, qy = qp[1] * K_LOG2E, qz = qp[2] * K_LOG2E;

    float* outp = out + ((long)b * PP + q0) * (TT * 3);

    #pragma unroll
    for (int t = 0; t < TT; t++) {
        const int s = sStart[t], e = sStart[t + 1];   // e-s multiple of 4
        float S0 = 0.f, Gx0 = 0.f, Gy0 = 0.f, Gz0 = 0.f;
        float S1 = 0.f, Gx1 = 0.f, Gy1 = 0.f, Gz1 = 0.f;

        // my half: atoms s+h, s+h+2, ... ; unroll-2 => two chains in flight
        for (int i = s + h; i < e; i += 4) {
            const float4 c0 = satoms[i];
            const float4 c1 = satoms[i + 2];

            float dx0 = c0.x - qx, dy0 = c0.y - qy, dz0 = c0.z - qz;
            float dx1 = c1.x - qx, dy1 = c1.y - qy, dz1 = c1.z - qz;

            float d20 = fmaf(dx0, dx0, fmaf(dy0, dy0, dz0 * dz0));
            float d21 = fmaf(dx1, dx1, fmaf(dy1, dy1, dz1 * dz1));

            float w0 = ex2f_a(-sqrtf_a(d20));
            float w1 = ex2f_a(-sqrtf_a(d21));

            S0 += w0;
            Gx0 = fmaf(w0, dx0, Gx0);
            Gy0 = fmaf(w0, dy0, Gy0);
            Gz0 = fmaf(w0, dz0, Gz0);

            S1 += w1;
            Gx1 = fmaf(w1, dx1, Gx1);
            Gy1 = fmaf(w1, dy1, Gy1);
            Gz1 = fmaf(w1, dz1, Gz1);
        }

        float S  = S0 + S1;
        float Gx = Gx0 + Gx1, Gy = Gy0 + Gy1, Gz = Gz0 + Gz1;

        // combine the two atom-halves (partner lane l^16 holds the other half)
        S  += __shfl_xor_sync(0xffffffffu, S, 16);
        Gx += __shfl_xor_sync(0xffffffffu, Gx, 16);
        Gy += __shfl_xor_sync(0xffffffffu, Gy, 16);
        Gz += __shfl_xor_sync(0xffffffffu, Gz, 16);

        // finalize: grad = (G/S)/log2(e); clip to norm 0.3; empty type -> 0
        // split the 5 stores between the two cooperating threads by parity of t
        if ((t & 1) == h) {
            float inv = (S > 0.f) ? rcpf_a(S) * LN2F : 0.f;
            float gx = Gx * inv, gy = Gy * inv, gz = Gz * inv;
            float m2 = fmaf(gx, gx, fmaf(gy, gy, gz * gz));
            if (m2 > CLIP * CLIP) {
                float sc = CLIP * rsqrtf_a(m2);
                gx *= sc; gy *= sc; gz *= sc;
            }
            outp[t * 3 + 0] = gx; outp[t * 3 + 1] = gy; outp[t * 3 + 2] = gz;
        }
    }
}

extern "C" void kernel_launch(void* const* d_in, const int* in_sizes, int n_in,
                              void* d_out, int out_size)
{
    const float* coords = (const float*)d_in[0];   // [16,128,3] f32
    const int*   types  = (const int*)d_in[1];     // [16,128] int32/int64 (detected on device)
    const float* query  = (const float*)d_in[2];   // [16,8192,3] f32
    float*       out    = (float*)d_out;           // [16,8192,5,3] f32

    dim3 grid(PP / QPB, BB);   // (64, 16) = 1024 blocks x 256 threads
    gnf_kernel<<<grid, THREADS>>>(coords, types, query, out);
}

// round 6
// speedup vs baseline: 1.0519x; 1.0173x over previous
#include <cuda_runtime.h>

// Problem constants (from reference)
#define BB 16
#define AA 128
#define PP 8192
#define TT 5
#define K_LOG2E 1.4426950408889634f   // log2(e); TEMPERATURE = 1.0
#define LN2F    0.6931471805599453f   // 1/log2(e)
#define CLIP    0.3f

#define THREADS 256          // 8 warps/block
#define QPB 128              // queries per block: 2 threads cooperate per query
#define MAXA 160             // 128 atoms + up to 5*3 pad, rounded up

__device__ __forceinline__ float ex2f_a(float x) {
    float y; asm("ex2.approx.ftz.f32 %0, %1;" : "=f"(y) : "f"(x)); return y;
}
__device__ __forceinline__ float sqrtf_a(float x) {
    float y; asm("sqrt.approx.ftz.f32 %0, %1;" : "=f"(y) : "f"(x)); return y;
}
__device__ __forceinline__ float rcpf_a(float x) {
    float y; asm("rcp.approx.ftz.f32 %0, %1;" : "=f"(y) : "f"(x)); return y;
}
__device__ __forceinline__ float rsqrtf_a(float x) {
    float y; asm("rsqrt.approx.ftz.f32 %0, %1;" : "=f"(y) : "f"(x)); return y;
}

__global__ void __launch_bounds__(THREADS, 8)   // clamp to 32 regs -> 64 warps/SM
gnf_kernel(const float* __restrict__ coords,     // [B, A, 3] f32
           const int*   __restrict__ types_raw,  // [B, A] int32 OR int64 (detected)
           const float* __restrict__ query,      // [B, P, 3] f32
           float*       __restrict__ out)        // [B, P, T, 3] f32
{
    // satoms[i] = (cx', cy', cz', |c'|^2) with c' = c * log2(e)
    __shared__ float4 satoms[MAXA];
    __shared__ int    sStart[TT + 1];   // padded starts, multiples of 4
    __shared__ int    sCnt[TT];
    __shared__ int    sOffs[TT];

    const int tid = threadIdx.x;
    const int b   = blockIdx.y;

    // ---- sentinel: c'=0, |c'|^2=1e30 -> d2 >= 1e30 -> w = ex2(-1e15) == 0, w*c = 0
    for (int j = tid; j < MAXA; j += THREADS)
        satoms[j] = make_float4(0.f, 0.f, 0.f, 1e30f);
    if (tid < TT) sCnt[tid] = 0;

    // ---- dtype detection: int64 iff every odd 32-bit word is 0 or -1
    bool ok = true;
    #pragma unroll 2
    for (int i = tid; i < (BB * AA) / 2; i += THREADS) {
        int w = types_raw[2 * i + 1];
        if (w != 0 && w != -1) ok = false;
    }
    const int is64 = __syncthreads_and(ok ? 1 : 0);  // also fences sentinel fill

    // ---- counting sort of this batch's 128 atoms by type, segments padded to x4
    int t_mine = -1;
    if (tid < AA) {
        long long tv;
        if (is64) tv = ((const long long*)types_raw)[(long)b * AA + tid];
        else      tv = (long long)types_raw[(long)b * AA + tid];
        if (tv >= 0 && tv < TT) {
            t_mine = (int)tv;
            atomicAdd(&sCnt[t_mine], 1);
        }
    }
    __syncthreads();
    if (tid == 0) {
        int s = 0;
        #pragma unroll
        for (int k = 0; k < TT; k++) {
            sStart[k] = s; sOffs[k] = s;
            s += (sCnt[k] + 3) & ~3;     // pad each segment to multiple of 4 atoms
        }
        sStart[TT] = s;
    }
    __syncthreads();
    if (t_mine >= 0) {
        int pos = atomicAdd(&sOffs[t_mine], 1);
        const float* c = coords + ((long)b * AA + tid) * 3;
        float cx = c[0] * K_LOG2E, cy = c[1] * K_LOG2E, cz = c[2] * K_LOG2E;
        satoms[pos] = make_float4(cx, cy, cz,
                                  fmaf(cx, cx, fmaf(cy, cy, cz * cz)));
    }
    __syncthreads();

    // ---- 2 threads per query: lanes l and l^16 share a query; h = atom half
    const int warp = tid >> 5;
    const int lane = tid & 31;
    const int h    = lane >> 4;
    const int q0   = blockIdx.x * QPB + warp * 16 + (lane & 15);

    const float* qp = query + ((long)b * PP + q0) * 3;
    const float qox = qp[0], qoy = qp[1], qoz = qp[2];       // original query (for epilogue)
    const float nx = qox * (-2.f * K_LOG2E);                 // -2*q'
    const float ny = qoy * (-2.f * K_LOG2E);
    const float nz = qoz * (-2.f * K_LOG2E);
    const float qq = -0.25f * fmaf(nx, nx, fmaf(ny, ny, nz * nz));  // |q'|^2... see note
    // note: |q'|^2 = (qox*L)^2+... = 0.25*(nx^2+ny^2+nz^2); sign fixed below
    const float qq2 = -qq;   // = +|q'|^2

    float* outp = out + ((long)b * PP + q0) * (TT * 3);

    #pragma unroll
    for (int t = 0; t < TT; t++) {
        const int s = sStart[t], e = sStart[t + 1];   // e-s multiple of 4
        float S0 = 0.f, Gx0 = 0.f, Gy0 = 0.f, Gz0 = 0.f;
        float S1 = 0.f, Gx1 = 0.f, Gy1 = 0.f, Gz1 = 0.f;

        // my half: atoms s+h, s+h+2, ...; unroll-2 => two sqrt->ex2 chains in flight
        for (int i = s + h; i < e; i += 4) {
            const float4 c0 = satoms[i];
            const float4 c1 = satoms[i + 2];

            // d2 = |c|^2 + |q|^2 - 2 c.q  (all in scaled coords)
            float d20 = fmaf(c0.x, nx, fmaf(c0.y, ny, fmaf(c0.z, nz, c0.w))) + qq2;
            float d21 = fmaf(c1.x, nx, fmaf(c1.y, ny, fmaf(c1.z, nz, c1.w))) + qq2;

            float w0 = ex2f_a(-sqrtf_a(d20));
            float w1 = ex2f_a(-sqrtf_a(d21));

            S0 += w0;
            Gx0 = fmaf(w0, c0.x, Gx0);
            Gy0 = fmaf(w0, c0.y, Gy0);
            Gz0 = fmaf(w0, c0.z, Gz0);

            S1 += w1;
            Gx1 = fmaf(w1, c1.x, Gx1);
            Gy1 = fmaf(w1, c1.y, Gy1);
            Gz1 = fmaf(w1, c1.z, Gz1);
        }

        float S  = S0 + S1;
        float Gx = Gx0 + Gx1, Gy = Gy0 + Gy1, Gz = Gz0 + Gz1;

        // combine the two atom-halves (partner lane l^16 holds the other half)
        S  += __shfl_xor_sync(0xffffffffu, S, 16);
        Gx += __shfl_xor_sync(0xffffffffu, Gx, 16);
        Gy += __shfl_xor_sync(0xffffffffu, Gy, 16);
        Gz += __shfl_xor_sync(0xffffffffu, Gz, 16);

        // finalize: grad = (Gc/S)/L - q_orig; clip to 0.3; empty type -> 0
        // split the 5 stores between the two cooperating threads by parity of t
        if ((t & 1) == h) {
            float gx = 0.f, gy = 0.f, gz = 0.f;
            if (S > 0.f) {
                float inv = rcpf_a(S) * LN2F;
                gx = fmaf(Gx, inv, -qox);
                gy = fmaf(Gy, inv, -qoy);
                gz = fmaf(Gz, inv, -qoz);
                float m2 = fmaf(gx, gx, fmaf(gy, gy, gz * gz));
                if (m2 > CLIP * CLIP) {
                    float sc = CLIP * rsqrtf_a(m2);
                    gx *= sc; gy *= sc; gz *= sc;
                }
            }
            outp[t * 3 + 0] = gx; outp[t * 3 + 1] = gy; outp[t * 3 + 2] = gz;
        }
    }
}

extern "C" void kernel_launch(void* const* d_in, const int* in_sizes, int n_in,
                              void* d_out, int out_size)
{
    const float* coords = (const float*)d_in[0];   // [16,128,3] f32
    const int*   types  = (const int*)d_in[1];     // [16,128] int32/int64 (detected on device)
    const float* query  = (const float*)d_in[2];   // [16,8192,3] f32
    float*       out    = (float*)d_out;           // [16,8192,5,3] f32

    dim3 grid(PP / QPB, BB);   // (64, 16) = 1024 blocks x 256 threads
    gnf_kernel<<<grid, THREADS>>>(coords, types, query, out);
}